// round 4
// baseline (speedup 1.0000x reference)
#include <cuda_runtime.h>
#include <cuda_bf16.h>

// RegionSelector: sampling_map [B=128, 1, 512, 512] fp32.
// GRID=4 -> 16 cells of 128x128. WIN=3 -> n=2 -> four 3x3 windows. TOPK=1.
// Output [B, 1, 2] = (row, col) of argmax window, written as FLOAT values
// (0.0/1.0) — hypothesis: harness output buffer is float32-typed.

#define B_    128
#define HW    512
#define HW4   (HW / 4)      // 128 float4 per image row
#define NT    512

__global__ __launch_bounds__(NT, 1)
void region_selector_kernel(const float* __restrict__ in, float* __restrict__ out) {
    const int b   = blockIdx.x;
    const int tid = threadIdx.x;

    const float4* __restrict__ base =
        reinterpret_cast<const float4*>(in + (size_t)b * (HW * HW));

    // tid = wid*32 + lane; c = tid & 127 -> float4 column (0..127)
    //   colcell = c >> 5 (uniform per warp), rphase = tid >> 7 (0..3)
    // Each thread: rows r = rowcell*128 + rphase + 4k, k = 0..31, rowcell 0..3.
    // Warp load = 32 consecutive float4 = 512B contiguous.
    const int c       = tid & 127;
    const int rphase  = tid >> 7;        // 0..3
    const int colcell = c >> 5;          // 0..3
    const int lane    = tid & 31;

    float s0 = 0.f, s1 = 0.f, s2 = 0.f, s3 = 0.f;

    #pragma unroll 4
    for (int k = 0; k < 32; k++) {
        const int r = rphase + 4 * k;            // 0..127 within a row-cell
        float4 v0 = base[(size_t)(r +   0) * HW4 + c];
        float4 v1 = base[(size_t)(r + 128) * HW4 + c];
        float4 v2 = base[(size_t)(r + 256) * HW4 + c];
        float4 v3 = base[(size_t)(r + 384) * HW4 + c];
        s0 += (v0.x + v0.y) + (v0.z + v0.w);
        s1 += (v1.x + v1.y) + (v1.z + v1.w);
        s2 += (v2.x + v2.y) + (v2.z + v2.w);
        s3 += (v3.x + v3.y) + (v3.z + v3.w);
    }

    // Warp reduce the 4 row-cell partial sums.
    #pragma unroll
    for (int off = 16; off > 0; off >>= 1) {
        s0 += __shfl_down_sync(0xFFFFFFFFu, s0, off);
        s1 += __shfl_down_sync(0xFFFFFFFFu, s1, off);
        s2 += __shfl_down_sync(0xFFFFFFFFu, s2, off);
        s3 += __shfl_down_sync(0xFFFFFFFFu, s3, off);
    }

    // partial[rowcell][colcell][rphase]: each written by one warp's lane 0.
    __shared__ float partial[4][4][4];
    __shared__ float cell[16];

    if (lane == 0) {
        partial[0][colcell][rphase] = s0;
        partial[1][colcell][rphase] = s1;
        partial[2][colcell][rphase] = s2;
        partial[3][colcell][rphase] = s3;
    }
    __syncthreads();

    if (tid < 16) {
        const int rc = tid >> 2;
        const int cc = tid & 3;
        cell[tid] = partial[rc][cc][0] + partial[rc][cc][1]
                  + partial[rc][cc][2] + partial[rc][cc][3];
    }
    __syncthreads();

    if (tid == 0) {
        // Four 3x3 windows over the 4x4 cell grid (n = 2). Argmax invariant
        // to the uniform 1/16384 mean scale, so raw sums suffice.
        float best = -3.402823466e+38f;
        int best_idx = 0;
        #pragma unroll
        for (int r = 0; r < 2; r++) {
            #pragma unroll
            for (int cw = 0; cw < 2; cw++) {
                float wsum = 0.f;
                #pragma unroll
                for (int dr = 0; dr < 3; dr++)
                    #pragma unroll
                    for (int dc = 0; dc < 3; dc++)
                        wsum += cell[(r + dr) * 4 + (cw + dc)];
                const int idx = r * 2 + cw;
                if (wsum > best) { best = wsum; best_idx = idx; }  // lowest idx wins ties
            }
        }
        // Write coordinates as FLOAT values (output buffer hypothesized float32).
        out[b * 2 + 0] = (float)(best_idx >> 1);   // row = idx / n
        out[b * 2 + 1] = (float)(best_idx & 1);    // col = idx % n
    }
}

extern "C" void kernel_launch(void* const* d_in, const int* in_sizes, int n_in,
                              void* d_out, int out_size) {
    const float* in = (const float*)d_in[0];
    float* out = (float*)d_out;
    region_selector_kernel<<<B_, NT>>>(in, out);
}